// round 13
// baseline (speedup 1.0000x reference)
#include <cuda_runtime.h>
#include <cuda_bf16.h>

#define QN      400
#define PN      200000
#define NLAB    100
#define KS      4
#define THREADS 128
#define CHUNK   (PN / KS)                 // 50000 (divisible by 16)
#define BINW    (NLAB * THREADS)          // 12800 bf16x2 bins = 50 KB
#define CVT_BLOCKS ((PN / 4 + 255) / 256) // 196

typedef unsigned long long u64;

// ---------------- device scratch (no allocation allowed) ----------------
__device__ unsigned char g_lab8[PN];
__device__ int   g_blockhist[CVT_BLOCKS * NLAB];
__device__ float g_partial[KS * QN * NLAB * 2];   // [r][q][lab][{d,s}]
__device__ float g_totals[KS * QN * 2];           // [r][q][{f0tot, ptot}]

// ---------------- kernel 0: narrow labels to u8 + per-block histogram ----------------
__global__ void convert_labels(const int* __restrict__ labels) {
    __shared__ int hist[NLAB];
    const int tid = threadIdx.x;
    for (int i = tid; i < NLAB; i += 256) hist[i] = 0;
    __syncthreads();

    int i = blockIdx.x * blockDim.x + tid;
    int base = i * 4;
    if (base < PN) {
        int4 l = *(const int4*)(labels + base);
        uchar4 u;
        u.x = (unsigned char)l.x; u.y = (unsigned char)l.y;
        u.z = (unsigned char)l.z; u.w = (unsigned char)l.w;
        *(uchar4*)(g_lab8 + base) = u;
        atomicAdd(&hist[l.x], 1); atomicAdd(&hist[l.y], 1);
        atomicAdd(&hist[l.z], 1); atomicAdd(&hist[l.w], 1);
    }
    __syncthreads();
    for (int j = tid; j < NLAB; j += 256)
        g_blockhist[blockIdx.x * NLAB + j] = hist[j];
}

// ---------------- packed f32x2 helpers (Blackwell sm_103a) ----------------
static __device__ __forceinline__ u64 mul2(u64 a, u64 b) {
    u64 r; asm("mul.rn.f32x2 %0,%1,%2;" : "=l"(r) : "l"(a), "l"(b)); return r;
}
static __device__ __forceinline__ u64 add2(u64 a, u64 b) {
    u64 r; asm("add.rn.f32x2 %0,%1,%2;" : "=l"(r) : "l"(a), "l"(b)); return r;
}
static __device__ __forceinline__ u64 fma2(u64 a, u64 b, u64 c) {
    u64 r; asm("fma.rn.f32x2 %0,%1,%2,%3;" : "=l"(r) : "l"(a), "l"(b), "l"(c)); return r;
}
static __device__ __forceinline__ u64 pk(float a, float b) {
    u64 r; asm("mov.b64 %0,{%1,%2};" : "=l"(r) : "f"(a), "f"(b)); return r;
}
static __device__ __forceinline__ void upk(u64 v, float& a, float& b) {
    asm("mov.b64 {%0,%1},%2;" : "=f"(a), "=f"(b) : "l"(v));
}

// packed constants (both halves identical, bit patterns)
#define C_NL2E 0xBFB8AA3BBFB8AA3BULL   // -log2(e)
#define C_ONE  0x3F8000003F800000ULL   //  1.0
#define C_NONE 0xBF800000BF800000ULL   // -1.0
#define C_NLN2 0xBF317218BF317218ULL   // -ln(2)
#define C_N075 0xBF400000BF400000ULL   // -0.75
#define C_N025 0xBE800000BE800000ULL   // -0.25

// ---- pair transform: 6 MUFU + 11 packed float ops for TWO elements ----
// Same math as scalar version (branch-free, safe |x| < 80); acc accumulates f0 packed.
static __device__ __forceinline__ void xform2(float x0, float x1, u64& acc,
                                              __nv_bfloat162& dp0, __nv_bfloat162& dp1) {
    u64 X = pk(x0, x1);
    float e0, e1; upk(mul2(X, C_NL2E), e0, e1);
    float t0, t1;
    asm("ex2.approx.f32 %0, %1;" : "=f"(t0) : "f"(e0));    // e^-x
    asm("ex2.approx.f32 %0, %1;" : "=f"(t1) : "f"(e1));
    u64 T = pk(t0, t1);
    float o0, o1; upk(add2(T, C_ONE), o0, o1);             // 1 + e^-x
    float p0, p1, g0, g1;
    asm("rcp.approx.f32 %0, %1;" : "=f"(p0) : "f"(o0));    // p = sigmoid(x)
    asm("rcp.approx.f32 %0, %1;" : "=f"(p1) : "f"(o1));
    asm("lg2.approx.f32 %0, %1;" : "=f"(g0) : "f"(o0));
    asm("lg2.approx.f32 %0, %1;" : "=f"(g1) : "f"(o1));
    u64 P = pk(p0, p1);
    u64 G = pk(g0, g1);
    u64 LOGP = mul2(G, C_NLN2);            // log sigmoid(x)
    u64 L1MP = fma2(X, C_NONE, LOGP);      // log sigmoid(-x) = logp - x
    u64 OMP  = mul2(T, P);                 // 1 - p (exact identity)
    u64 U = mul2(P, P);
    u64 V = mul2(OMP, OMP);
    u64 F0 = mul2(U, mul2(L1MP, C_N075));  // f0 = -0.75 p^2 l1mp
    u64 F1 = mul2(V, mul2(LOGP, C_N025));  // f1 = -0.25 (1-p)^2 logp
    u64 D  = fma2(F0, C_NONE, F1);         // d = f1 - f0
    acc = add2(acc, F0);
    float d0, d1; upk(D, d0, d1);
    dp0 = __floats2bfloat162_rn(d0, p0);   // .x=d, .y=p
    dp1 = __floats2bfloat162_rn(d1, p1);
}

// ---------------- kernel 1: main segmented reduction (width-16, packed math) ----------------
__global__ __launch_bounds__(THREADS, 4)
void main_kernel(const float* __restrict__ pred) {
    extern __shared__ __nv_bfloat162 sb[];   // [NLAB][THREADS], bank = tid%32
    const int tid = threadIdx.x;
    const int q = blockIdx.x;
    const int r = blockIdx.y;

    uint4* z4 = (uint4*)sb;
    #pragma unroll 4
    for (int i = tid; i < BINW / 4; i += THREADS)
        z4[i] = make_uint4(0u, 0u, 0u, 0u);
    __syncthreads();

    const float* row = pred + (size_t)q * PN + (size_t)r * CHUNK;
    const unsigned char* lab = g_lab8 + r * CHUNK;
    __nv_bfloat162* const bbase = sb + tid;

    u64 acc = 0ULL;                          // packed (0.0f, 0.0f)
    const int S = THREADS * 16;              // 2048

    // ---- prefetch first 16-element group (4x LDG.128 pred + 1x LDG.128 labels) ----
    int idx = tid * 16;
    float4 A0, A1, A2, A3; uint4 LW;
    if (idx < CHUNK) {
        A0 = __ldcs((const float4*)(row + idx));
        A1 = __ldcs((const float4*)(row + idx + 4));
        A2 = __ldcs((const float4*)(row + idx + 8));
        A3 = __ldcs((const float4*)(row + idx + 12));
        LW = *(const uint4*)(lab + idx);
    }

    while (idx < CHUNK) {
        int nidx = idx + S;
        float4 B0, B1, B2, B3; uint4 NLW;
        if (nidx < CHUNK) {                  // next group's loads in flight during body
            B0 = __ldcs((const float4*)(row + nidx));
            B1 = __ldcs((const float4*)(row + nidx + 4));
            B2 = __ldcs((const float4*)(row + nidx + 8));
            B3 = __ldcs((const float4*)(row + nidx + 12));
            NLW = *(const uint4*)(lab + nidx);
        }

        __nv_bfloat162 dp[16];
        xform2(A0.x, A0.y, acc, dp[0],  dp[1]);
        xform2(A0.z, A0.w, acc, dp[2],  dp[3]);
        xform2(A1.x, A1.y, acc, dp[4],  dp[5]);
        xform2(A1.z, A1.w, acc, dp[6],  dp[7]);
        xform2(A2.x, A2.y, acc, dp[8],  dp[9]);
        xform2(A2.z, A2.w, acc, dp[10], dp[11]);
        xform2(A3.x, A3.y, acc, dp[12], dp[13]);
        xform2(A3.z, A3.w, acc, dp[14], dp[15]);

        unsigned lw[4] = {LW.x, LW.y, LW.z, LW.w};
        #pragma unroll
        for (int i = 0; i < 16; i++) {
            int l = (int)((lw[i >> 2] >> (8 * (i & 3))) & 0xffu);
            __nv_bfloat162* bp = bbase + l * THREADS;
            *bp = __hadd2(*bp, dp[i]);
        }

        A0 = B0; A1 = B1; A2 = B2; A3 = B3; LW = NLW;
        idx = nidx;
    }

    float a0, a1; upk(acc, a0, a1);
    float accf0 = a0 + a1;
    __syncthreads();

    // reduce 128 lanes per label -> deterministic partial buffer (exact f32)
    float ss = 0.f;
    if (tid < NLAB) {
        float ds = 0.f;
        #pragma unroll 4
        for (int i = 0; i < THREADS; i++) {
            float2 v = __bfloat1622float2(sb[tid * THREADS + ((i + tid) & (THREADS - 1))]);
            ds += v.x; ss += v.y;
        }
        int o = ((r * QN + q) * NLAB + tid) * 2;
        g_partial[o]     = ds;
        g_partial[o + 1] = ss;
    }
    __syncthreads();

    // total p = sum of ss over all labels (every point has exactly one label)
    float* sred = (float*)sb;
    sred[tid] = ss;
    __syncthreads();
    #pragma unroll
    for (int s = THREADS / 2; s >= 32; s >>= 1) {
        if (tid < s) sred[tid] += sred[tid + s];
        __syncthreads();
    }
    if (tid < 32) {
        float v = sred[tid];
        #pragma unroll
        for (int off = 16; off; off >>= 1) v += __shfl_down_sync(0xffffffffu, v, off);
        if (tid == 0) g_totals[(r * QN + q) * 2 + 1] = v;
    }

    // row total f0 (exact f32 path)
    #pragma unroll
    for (int off = 16; off; off >>= 1)
        accf0 += __shfl_down_sync(0xffffffffu, accf0, off);
    __shared__ float ws[4];
    if ((tid & 31) == 0) ws[tid >> 5] = accf0;
    __syncthreads();
    if (tid == 0) {
        float f = ws[0] + ws[1] + ws[2] + ws[3];
        g_totals[(r * QN + q) * 2 + 0] = f;
    }
}

// ---------------- kernel 2: counts + cost assembly ----------------
__global__ void finalize(float* __restrict__ out) {
    const int j = blockIdx.x;           // label 0..99
    const int tid = threadIdx.x;        // 256 threads

    int c = 0;
    for (int b = tid; b < CVT_BLOCKS; b += 256)
        c += g_blockhist[b * NLAB + j];
    #pragma unroll
    for (int off = 16; off; off >>= 1) c += __shfl_down_sync(0xffffffffu, c, off);
    __shared__ int cs[8];
    if ((tid & 31) == 0) cs[tid >> 5] = c;
    __syncthreads();
    int cnt = 0;
    #pragma unroll
    for (int w = 0; w < 8; w++) cnt += cs[w];
    float fc = (float)cnt;

    for (int q = tid; q < QN; q += 256) {
        float dsum = 0.f, ssum = 0.f, f0t = 0.f, pt = 0.f;
        #pragma unroll
        for (int r = 0; r < KS; r++) {
            int bi = ((r * QN + q) * NLAB + j) * 2;
            dsum += g_partial[bi];
            ssum += g_partial[bi + 1];
            f0t  += g_totals[(r * QN + q) * 2 + 0];
            pt   += g_totals[(r * QN + q) * 2 + 1];
        }
        float cmask = (dsum + f0t) * (1.0f / (float)PN);
        float dice  = 1.0f - (2.0f * ssum + 1.0f) / (pt + fc + 1.0f);
        out[q * NLAB + j] = cmask + dice;
    }
}

// ---------------- launch ----------------
extern "C" void kernel_launch(void* const* d_in, const int* in_sizes, int n_in,
                              void* d_out, int out_size) {
    const float* pred  = (const float*)d_in[0];
    const int* labels  = (const int*)d_in[1];
    float* out = (float*)d_out;

    cudaFuncSetAttribute(main_kernel,
                         cudaFuncAttributeMaxDynamicSharedMemorySize,
                         BINW * (int)sizeof(__nv_bfloat162));

    convert_labels<<<CVT_BLOCKS, 256>>>(labels);
    dim3 grid(QN, KS);
    main_kernel<<<grid, THREADS, BINW * sizeof(__nv_bfloat162)>>>(pred);
    finalize<<<NLAB, 256>>>(out);
}